// round 4
// baseline (speedup 1.0000x reference)
#include <cuda_runtime.h>
#include <cstdint>

// ---------------------------------------------------------------------------
// S = q @ k^T  [8192,8192];  G = gelu_exact(S/||S||_row*sqrt(8192));
// out = G @ v  [8192,1024].
// tf32 mma.sync + cp.async 3-stage pipeline. All GEMM operands staged in
// global pre-rounded to tf32 (cvt.rna) AND k-pair-permuted (groups of 8 k
// stored as k0,k4,k1,k5,k2,k6,k3,k7) so inner-loop fragment loads are LDS.64
// with zero cvt. tcgen05 is unusable here (harness emits compute_103 PTX).
// ---------------------------------------------------------------------------

static __device__ float g_S [8192ull * 8192ull];  // 256 MB scores/gated (k-permuted cols)
static __device__ float g_VT[1024ull * 8192ull];  // 32 MB  v^T (rounded, k-permuted)
static __device__ float g_QT[8192ull * 1024ull];  // 32 MB  q  (rounded, k-permuted)
static __device__ float g_KT[8192ull * 1024ull];  // 32 MB  k  (rounded, k-permuted)

__device__ __forceinline__ float f2tf32f(float x) {
    uint32_t u;
    asm("cvt.rna.tf32.f32 %0, %1;" : "=r"(u) : "f"(x));
    return __uint_as_float(u);
}

// ---------------------------------------------------------------------------
// GEMM: C[M,N] = A[M,K] * B[N,K]^T, operands tf32-valued & k-pair-permuted.
// Block 128x128x32, 8 warps (4M x 2N), warp tile 32x64.
// PERMC: store C with columns permuted within 8-groups (for S feeding GEMM2).
// ---------------------------------------------------------------------------
constexpr int BM = 128, BN = 128, BK = 32, SPAD = 4;
constexpr int SLD = BK + SPAD;          // 36 words
constexpr int STAGES = 3;
constexpr int TILEA = BM * SLD;
constexpr int TILE2 = 2 * TILEA;
constexpr unsigned SMEM_BYTES = STAGES * TILE2 * 4;  // 110,592 B

__device__ __forceinline__ void cp16(uint32_t dst_s, const float* src) {
    asm volatile("cp.async.cg.shared.global [%0], [%1], 16;\n" :: "r"(dst_s), "l"(src));
}

template <bool PERMC>
__global__ __launch_bounds__(256, 2) void gemm_tf32_pipe(
    const float* __restrict__ A, const float* __restrict__ B, float* __restrict__ C,
    int M, int N, int K)
{
    extern __shared__ float smem[];
    const uint32_t smem_s = (uint32_t)__cvta_generic_to_shared(smem);

    const int tid  = threadIdx.x;
    const int lane = tid & 31;
    const int wid  = tid >> 5;
    const int wm   = wid & 3;     // 0..3 along M
    const int wn   = wid >> 2;    // 0..1 along N
    const long bm = (long)blockIdx.y * BM;
    const long bn = (long)blockIdx.x * BN;

    float acc[2][8][4];
#pragma unroll
    for (int i = 0; i < 2; i++)
#pragma unroll
        for (int j = 0; j < 8; j++)
#pragma unroll
            for (int c = 0; c < 4; c++) acc[i][j][c] = 0.f;

    const int nk = K / BK;

    auto load_stage = [&](int s, int kt) {
        const uint32_t sA = smem_s + (uint32_t)(s * TILE2) * 4u;
        const uint32_t sB = sA + (uint32_t)TILEA * 4u;
        const int k0 = kt * BK;
#pragma unroll
        for (int i = 0; i < 4; i++) {
            int idx = tid + i * 256;          // 0..1023
            int row = idx >> 3;               // 0..127
            int c4  = (idx & 7) << 2;         // 0,4,...,28
            cp16(sA + (uint32_t)(row * SLD + c4) * 4u,
                 &A[(size_t)(bm + row) * K + k0 + c4]);
            cp16(sB + (uint32_t)(row * SLD + c4) * 4u,
                 &B[(size_t)(bn + row) * K + k0 + c4]);
        }
        asm volatile("cp.async.commit_group;\n");
    };

#pragma unroll
    for (int s = 0; s < STAGES - 1; s++) load_stage(s, s);

    const int tk2 = (lane & 3) * 2;
    const int qrow = lane >> 2;

    for (int kt = 0; kt < nk; kt++) {
        asm volatile("cp.async.wait_group %0;\n" :: "n"(STAGES - 2));
        __syncthreads();

        if (kt + STAGES - 1 < nk) {
            load_stage((kt + STAGES - 1) % STAGES, kt + STAGES - 1);
        } else {
            asm volatile("cp.async.commit_group;\n");
        }

        const float* As = smem + (kt % STAGES) * TILE2;
        const float* Bs = As + TILEA;

#pragma unroll
        for (int ks = 0; ks < 4; ks++) {
            const int kk = ks * 8 + tk2;
            // A fragments: (a0,a2) from row r, (a1,a3) from row r+8 — LDS.64
            float2 pa[2], pa8[2];
#pragma unroll
            for (int mt = 0; mt < 2; mt++) {
                int r = wm * 32 + mt * 16 + qrow;
                pa[mt]  = *reinterpret_cast<const float2*>(&As[(r    ) * SLD + kk]);
                pa8[mt] = *reinterpret_cast<const float2*>(&As[(r + 8) * SLD + kk]);
            }
#pragma unroll
            for (int nt = 0; nt < 8; nt++) {
                int cidx = wn * 64 + nt * 8 + qrow;
                float2 pb = *reinterpret_cast<const float2*>(&Bs[cidx * SLD + kk]);
                uint32_t b0 = __float_as_uint(pb.x), b1 = __float_as_uint(pb.y);
#pragma unroll
                for (int mt = 0; mt < 2; mt++) {
                    asm volatile(
                        "mma.sync.aligned.m16n8k8.row.col.f32.tf32.tf32.f32 "
                        "{%0,%1,%2,%3}, {%4,%5,%6,%7}, {%8,%9}, {%0,%1,%2,%3};\n"
                        : "+f"(acc[mt][nt][0]), "+f"(acc[mt][nt][1]),
                          "+f"(acc[mt][nt][2]), "+f"(acc[mt][nt][3])
                        : "r"(__float_as_uint(pa[mt].x)),
                          "r"(__float_as_uint(pa8[mt].x)),
                          "r"(__float_as_uint(pa[mt].y)),
                          "r"(__float_as_uint(pa8[mt].y)),
                          "r"(b0), "r"(b1));
                }
            }
        }
    }

    // ---- epilogue ----
    const int t = lane & 3;
    // permuted position of logical col 2t within its 8-group: p0; col 2t+1 -> p0+2
    const int p0 = (t < 2) ? 4 * t : 4 * t - 7;
#pragma unroll
    for (int mt = 0; mt < 2; mt++) {
        long r0 = bm + wm * 32 + mt * 16 + qrow;
#pragma unroll
        for (int nt = 0; nt < 8; nt++) {
            long base = bn + wn * 64 + nt * 8;
            if (PERMC) {
                C[(size_t)r0 * N + base + p0]            = acc[mt][nt][0];
                C[(size_t)r0 * N + base + p0 + 2]        = acc[mt][nt][1];
                C[(size_t)(r0 + 8) * N + base + p0]      = acc[mt][nt][2];
                C[(size_t)(r0 + 8) * N + base + p0 + 2]  = acc[mt][nt][3];
            } else {
                long c0 = base + 2 * t;
                *reinterpret_cast<float2*>(&C[(size_t)r0 * N + c0]) =
                    make_float2(acc[mt][nt][0], acc[mt][nt][1]);
                *reinterpret_cast<float2*>(&C[(size_t)(r0 + 8) * N + c0]) =
                    make_float2(acc[mt][nt][2], acc[mt][nt][3]);
            }
        }
    }
}

// ---------------------------------------------------------------------------
// Stage q/k: tf32-round + k-pair-permute (each 8-group -> k0,k4,k1,k5,k2,k6,k3,k7)
// One thread per 8-float group; fully vectorized.
// ---------------------------------------------------------------------------
__global__ __launch_bounds__(256) void stage_pairs_kernel(
    const float4* __restrict__ in, float4* __restrict__ out, int ngroups)
{
    int g = blockIdx.x * 256 + threadIdx.x;
    if (g >= ngroups) return;
    float4 a = in[2 * g];       // k0..k3
    float4 b = in[2 * g + 1];   // k4..k7
    out[2 * g]     = make_float4(f2tf32f(a.x), f2tf32f(b.x), f2tf32f(a.y), f2tf32f(b.y));
    out[2 * g + 1] = make_float4(f2tf32f(a.z), f2tf32f(b.z), f2tf32f(a.w), f2tf32f(b.w));
}

// ---------------------------------------------------------------------------
// Row L2-norm * sqrt(N) + exact GELU in place; output tf32-rounded.
// (S columns are k-permuted; permutation-invariant for the norm, elementwise GELU.)
// ---------------------------------------------------------------------------
__global__ __launch_bounds__(256) void norm_gelu_kernel(float* __restrict__ S, int N)
{
    float4* p = reinterpret_cast<float4*>(S + (size_t)blockIdx.x * N);
    const int n4 = N >> 2;
    float ss = 0.f;
    for (int i = threadIdx.x; i < n4; i += 256) {
        float4 x = p[i];
        ss += x.x * x.x + x.y * x.y + x.z * x.z + x.w * x.w;
    }
    __shared__ float red[8];
#pragma unroll
    for (int o = 16; o > 0; o >>= 1) ss += __shfl_xor_sync(0xffffffffu, ss, o);
    if ((threadIdx.x & 31) == 0) red[threadIdx.x >> 5] = ss;
    __syncthreads();
    if (threadIdx.x < 32) {
        float v = (threadIdx.x < 8) ? red[threadIdx.x] : 0.f;
#pragma unroll
        for (int o = 4; o > 0; o >>= 1) v += __shfl_xor_sync(0xffffffffu, v, o);
        if (threadIdx.x == 0) red[0] = v;
    }
    __syncthreads();
    const float scale = sqrtf((float)N / red[0]);
    const float inv_sqrt2 = 0.70710678118654752440f;
    for (int i = threadIdx.x; i < n4; i += 256) {
        float4 x = p[i];
        x.x *= scale; x.y *= scale; x.z *= scale; x.w *= scale;
        x.x = f2tf32f(0.5f * x.x * (1.f + erff(x.x * inv_sqrt2)));
        x.y = f2tf32f(0.5f * x.y * (1.f + erff(x.y * inv_sqrt2)));
        x.z = f2tf32f(0.5f * x.z * (1.f + erff(x.z * inv_sqrt2)));
        x.w = f2tf32f(0.5f * x.w * (1.f + erff(x.w * inv_sqrt2)));
        p[i] = x;
    }
}

// ---------------------------------------------------------------------------
// Transpose v[8192,1024] -> vT[1024,8192], tf32-rounded + k-pair-permuted cols.
// ---------------------------------------------------------------------------
__global__ __launch_bounds__(256) void transpose_kernel(
    const float* __restrict__ V, float* __restrict__ VT, int R, int Ccols)
{
    __shared__ float tbuf[32][33];
    int c0 = blockIdx.x * 32, r0 = blockIdx.y * 32;
    int x = threadIdx.x, y = threadIdx.y;  // block (32,8)
#pragma unroll
    for (int j = 0; j < 32; j += 8)
        tbuf[y + j][x] = V[(size_t)(r0 + y + j) * Ccols + c0 + x];
    __syncthreads();
    // permuted k position for lane x within its 8-group
    int xg = x & 7;
    int px = (x & ~7) + ((xg & 3) << 1) + (xg >> 2);
#pragma unroll
    for (int j = 0; j < 32; j += 8)
        VT[(size_t)(c0 + y + j) * R + r0 + px] = f2tf32f(tbuf[x][y + j]);
}

// ---------------------------------------------------------------------------
extern "C" void kernel_launch(void* const* d_in, const int* in_sizes, int n_in,
                              void* d_out, int out_size)
{
    const float* q = (const float*)d_in[0];   // [8192, 1024]
    const float* k = (const float*)d_in[1];   // [8192, 1024]
    const float* v = (const float*)d_in[2];   // [8192, 1024]
    float* out = (float*)d_out;               // [8192, 1024]

    float *S, *VT, *QT, *KT;
    cudaGetSymbolAddress((void**)&S,  g_S);
    cudaGetSymbolAddress((void**)&VT, g_VT);
    cudaGetSymbolAddress((void**)&QT, g_QT);
    cudaGetSymbolAddress((void**)&KT, g_KT);

    static bool attr_done = false;
    if (!attr_done) {
        cudaFuncSetAttribute(gemm_tf32_pipe<true>,
                             cudaFuncAttributeMaxDynamicSharedMemorySize, SMEM_BYTES);
        cudaFuncSetAttribute(gemm_tf32_pipe<false>,
                             cudaFuncAttributeMaxDynamicSharedMemorySize, SMEM_BYTES);
        attr_done = true;
    }

    const int M = 8192, NBANK = 8192, D = 1024;
    const int ngroups = (M * D) / 8;

    // stage operands: round + permute
    stage_pairs_kernel<<<(ngroups + 255) / 256, 256>>>((const float4*)q, (float4*)QT, ngroups);
    stage_pairs_kernel<<<(ngroups + 255) / 256, 256>>>((const float4*)k, (float4*)KT, ngroups);
    transpose_kernel<<<dim3(D / 32, NBANK / 32), dim3(32, 8)>>>(v, VT, NBANK, D);

    // S = q @ k^T  (store with permuted columns = GEMM2's k layout)
    gemm_tf32_pipe<true><<<dim3(NBANK / BN, M / BM), 256, SMEM_BYTES>>>(QT, KT, S, M, NBANK, D);

    // norm + exact gelu in place (rounds output to tf32)
    norm_gelu_kernel<<<M, 256>>>(S, NBANK);

    // out = G @ vT^T  (normal output layout)
    gemm_tf32_pipe<false><<<dim3(D / BN, M / BM), 256, SMEM_BYTES>>>(S, VT, out, M, D, NBANK);
}

// round 5
// speedup vs baseline: 1.1941x; 1.1941x over previous
#include <cuda_runtime.h>
#include <cstdint>

// ---------------------------------------------------------------------------
// S = q @ k^T  [8192,8192];  G = gelu_exact(S/||S||_row*sqrt(8192));
// out = G @ v  [8192,1024].
// tf32 mma.sync + cp.async 3-stage pipeline. Operands staged in global
// pre-rounded to tf32 (cvt.rna) and k-pair-permuted (8-groups stored as
// k0,k4,k1,k5,k2,k6,k3,k7) so all fragment loads are LDS.64 with zero cvt.
// SLD=40 words makes every LDS.64 pattern bank-conflict-free.
// CTA: 512 threads, tile 256x128 (fits 3 stages x 60KB in one CTA's smem).
// ---------------------------------------------------------------------------

static __device__ float g_S [8192ull * 8192ull];  // 256 MB scores/gated (perm cols)
static __device__ float g_VT[1024ull * 8192ull];  // 32 MB  v^T (rounded, perm)
static __device__ float g_QT[8192ull * 1024ull];  // 32 MB  q  (rounded, perm)
static __device__ float g_KT[8192ull * 1024ull];  // 32 MB  k  (rounded, perm)

__device__ __forceinline__ float f2tf32f(float x) {
    uint32_t u;
    asm("cvt.rna.tf32.f32 %0, %1;" : "=r"(u) : "f"(x));
    return __uint_as_float(u);
}

// ---------------------------------------------------------------------------
// GEMM: C[M,N] = A[M,K] * B[N,K]^T, operands tf32-valued & k-pair-permuted.
// Block 256x128x32, 16 warps (8M x 2N), warp tile 32x64.
// ---------------------------------------------------------------------------
constexpr int BM = 256, BN = 128, BK = 32;
constexpr int SLD = 40;                  // conflict-free stride for LDS.64
constexpr int STAGES = 3;
constexpr int TILEA = BM * SLD;          // 10240 floats
constexpr int TILEB = BN * SLD;          // 5120 floats
constexpr int STAGE = TILEA + TILEB;     // 15360 floats
constexpr unsigned SMEM_BYTES = STAGES * STAGE * 4;  // 184320 B

__device__ __forceinline__ void cp16(uint32_t dst_s, const float* src) {
    asm volatile("cp.async.cg.shared.global [%0], [%1], 16;\n" :: "r"(dst_s), "l"(src));
}

template <bool PERMC>
__global__ __launch_bounds__(512, 1) void gemm_tf32_pipe(
    const float* __restrict__ A, const float* __restrict__ B, float* __restrict__ C,
    int M, int N, int K)
{
    extern __shared__ float smem[];
    const uint32_t smem_s = (uint32_t)__cvta_generic_to_shared(smem);

    const int tid  = threadIdx.x;
    const int lane = tid & 31;
    const int wid  = tid >> 5;
    const int wm   = wid & 7;     // 0..7 along M
    const int wn   = wid >> 3;    // 0..1 along N
    const long bm = (long)blockIdx.y * BM;
    const long bn = (long)blockIdx.x * BN;

    float acc[2][8][4];
#pragma unroll
    for (int i = 0; i < 2; i++)
#pragma unroll
        for (int j = 0; j < 8; j++)
#pragma unroll
            for (int c = 0; c < 4; c++) acc[i][j][c] = 0.f;

    const int nk = K / BK;

    auto load_stage = [&](int s, int kt) {
        const uint32_t sA = smem_s + (uint32_t)(s * STAGE) * 4u;
        const uint32_t sB = sA + (uint32_t)TILEA * 4u;
        const int k0 = kt * BK;
#pragma unroll
        for (int i = 0; i < 4; i++) {              // A: 256 rows x 32 floats
            int idx = tid + i * 512;               // 0..2047
            int row = idx >> 3;
            int c4  = (idx & 7) << 2;
            cp16(sA + (uint32_t)(row * SLD + c4) * 4u,
                 &A[(size_t)(bm + row) * K + k0 + c4]);
        }
#pragma unroll
        for (int i = 0; i < 2; i++) {              // B: 128 rows x 32 floats
            int idx = tid + i * 512;               // 0..1023
            int row = idx >> 3;
            int c4  = (idx & 7) << 2;
            cp16(sB + (uint32_t)(row * SLD + c4) * 4u,
                 &B[(size_t)(bn + row) * K + k0 + c4]);
        }
        asm volatile("cp.async.commit_group;\n");
    };

#pragma unroll
    for (int s = 0; s < STAGES - 1; s++) load_stage(s, s);

    const int t    = lane & 3;
    const int tk2  = t * 2;
    const int qrow = lane >> 2;

    for (int kt = 0; kt < nk; kt++) {
        asm volatile("cp.async.wait_group %0;\n" :: "n"(STAGES - 2));
        __syncthreads();

        if (kt + STAGES - 1 < nk) {
            load_stage((kt + STAGES - 1) % STAGES, kt + STAGES - 1);
        } else {
            asm volatile("cp.async.commit_group;\n");
        }

        const float* As = smem + (kt % STAGES) * STAGE;
        const float* Bs = As + TILEA;

#pragma unroll
        for (int ks = 0; ks < 4; ks++) {
            const int kk = ks * 8 + tk2;
            float2 pa[2], pa8[2];
#pragma unroll
            for (int mt = 0; mt < 2; mt++) {
                int r = wm * 32 + mt * 16 + qrow;
                pa[mt]  = *reinterpret_cast<const float2*>(&As[(r    ) * SLD + kk]);
                pa8[mt] = *reinterpret_cast<const float2*>(&As[(r + 8) * SLD + kk]);
            }
#pragma unroll
            for (int nt = 0; nt < 8; nt++) {
                int cidx = wn * 64 + nt * 8 + qrow;
                float2 pb = *reinterpret_cast<const float2*>(&Bs[cidx * SLD + kk]);
                uint32_t b0 = __float_as_uint(pb.x), b1 = __float_as_uint(pb.y);
#pragma unroll
                for (int mt = 0; mt < 2; mt++) {
                    asm volatile(
                        "mma.sync.aligned.m16n8k8.row.col.f32.tf32.tf32.f32 "
                        "{%0,%1,%2,%3}, {%4,%5,%6,%7}, {%8,%9}, {%0,%1,%2,%3};\n"
                        : "+f"(acc[mt][nt][0]), "+f"(acc[mt][nt][1]),
                          "+f"(acc[mt][nt][2]), "+f"(acc[mt][nt][3])
                        : "r"(__float_as_uint(pa[mt].x)),
                          "r"(__float_as_uint(pa8[mt].x)),
                          "r"(__float_as_uint(pa[mt].y)),
                          "r"(__float_as_uint(pa8[mt].y)),
                          "r"(b0), "r"(b1));
                }
            }
        }
    }

    // ---- epilogue ----
    // permuted position of logical col 2t within its 8-group; col 2t+1 -> +2
    const int p0 = (t < 2) ? 4 * t : 4 * t - 7;
#pragma unroll
    for (int mt = 0; mt < 2; mt++) {
        long r0 = bm + wm * 32 + mt * 16 + qrow;
#pragma unroll
        for (int nt = 0; nt < 8; nt++) {
            long base = bn + wn * 64 + nt * 8;
            if (PERMC) {
                C[(size_t)r0 * N + base + p0]            = acc[mt][nt][0];
                C[(size_t)r0 * N + base + p0 + 2]        = acc[mt][nt][1];
                C[(size_t)(r0 + 8) * N + base + p0]      = acc[mt][nt][2];
                C[(size_t)(r0 + 8) * N + base + p0 + 2]  = acc[mt][nt][3];
            } else {
                long c0 = base + 2 * t;
                *reinterpret_cast<float2*>(&C[(size_t)r0 * N + c0]) =
                    make_float2(acc[mt][nt][0], acc[mt][nt][1]);
                *reinterpret_cast<float2*>(&C[(size_t)(r0 + 8) * N + c0]) =
                    make_float2(acc[mt][nt][2], acc[mt][nt][3]);
            }
        }
    }
}

// ---------------------------------------------------------------------------
// Stage q/k: tf32-round + k-pair-permute (8-group -> k0,k4,k1,k5,k2,k6,k3,k7)
// ---------------------------------------------------------------------------
__global__ __launch_bounds__(256) void stage_pairs_kernel(
    const float4* __restrict__ in, float4* __restrict__ out, int ngroups)
{
    int g = blockIdx.x * 256 + threadIdx.x;
    if (g >= ngroups) return;
    float4 a = in[2 * g];       // k0..k3
    float4 b = in[2 * g + 1];   // k4..k7
    out[2 * g]     = make_float4(f2tf32f(a.x), f2tf32f(b.x), f2tf32f(a.y), f2tf32f(b.y));
    out[2 * g + 1] = make_float4(f2tf32f(a.z), f2tf32f(b.z), f2tf32f(a.w), f2tf32f(b.w));
}

// ---------------------------------------------------------------------------
// Row L2-norm * sqrt(N) + exact GELU in place; output tf32-rounded.
// (S columns k-permuted; norm is permutation-invariant, GELU elementwise.)
// ---------------------------------------------------------------------------
__global__ __launch_bounds__(256) void norm_gelu_kernel(float* __restrict__ S, int N)
{
    float4* p = reinterpret_cast<float4*>(S + (size_t)blockIdx.x * N);
    const int n4 = N >> 2;
    float ss = 0.f;
    for (int i = threadIdx.x; i < n4; i += 256) {
        float4 x = p[i];
        ss += x.x * x.x + x.y * x.y + x.z * x.z + x.w * x.w;
    }
    __shared__ float red[8];
#pragma unroll
    for (int o = 16; o > 0; o >>= 1) ss += __shfl_xor_sync(0xffffffffu, ss, o);
    if ((threadIdx.x & 31) == 0) red[threadIdx.x >> 5] = ss;
    __syncthreads();
    if (threadIdx.x < 32) {
        float v = (threadIdx.x < 8) ? red[threadIdx.x] : 0.f;
#pragma unroll
        for (int o = 4; o > 0; o >>= 1) v += __shfl_xor_sync(0xffffffffu, v, o);
        if (threadIdx.x == 0) red[0] = v;
    }
    __syncthreads();
    const float scale = sqrtf((float)N / red[0]);
    const float inv_sqrt2 = 0.70710678118654752440f;
    for (int i = threadIdx.x; i < n4; i += 256) {
        float4 x = p[i];
        x.x *= scale; x.y *= scale; x.z *= scale; x.w *= scale;
        x.x = f2tf32f(0.5f * x.x * (1.f + erff(x.x * inv_sqrt2)));
        x.y = f2tf32f(0.5f * x.y * (1.f + erff(x.y * inv_sqrt2)));
        x.z = f2tf32f(0.5f * x.z * (1.f + erff(x.z * inv_sqrt2)));
        x.w = f2tf32f(0.5f * x.w * (1.f + erff(x.w * inv_sqrt2)));
        p[i] = x;
    }
}

// ---------------------------------------------------------------------------
// Transpose v[8192,1024] -> vT[1024,8192], tf32-rounded + k-pair-permuted.
// ---------------------------------------------------------------------------
__global__ __launch_bounds__(256) void transpose_kernel(
    const float* __restrict__ V, float* __restrict__ VT, int R, int Ccols)
{
    __shared__ float tbuf[32][33];
    int c0 = blockIdx.x * 32, r0 = blockIdx.y * 32;
    int x = threadIdx.x, y = threadIdx.y;  // block (32,8)
#pragma unroll
    for (int j = 0; j < 32; j += 8)
        tbuf[y + j][x] = V[(size_t)(r0 + y + j) * Ccols + c0 + x];
    __syncthreads();
    int xg = x & 7;
    int px = (x & ~7) + ((xg & 3) << 1) + (xg >> 2);
#pragma unroll
    for (int j = 0; j < 32; j += 8)
        VT[(size_t)(c0 + y + j) * R + r0 + px] = f2tf32f(tbuf[x][y + j]);
}

// ---------------------------------------------------------------------------
extern "C" void kernel_launch(void* const* d_in, const int* in_sizes, int n_in,
                              void* d_out, int out_size)
{
    const float* q = (const float*)d_in[0];   // [8192, 1024]
    const float* k = (const float*)d_in[1];   // [8192, 1024]
    const float* v = (const float*)d_in[2];   // [8192, 1024]
    float* out = (float*)d_out;               // [8192, 1024]

    float *S, *VT, *QT, *KT;
    cudaGetSymbolAddress((void**)&S,  g_S);
    cudaGetSymbolAddress((void**)&VT, g_VT);
    cudaGetSymbolAddress((void**)&QT, g_QT);
    cudaGetSymbolAddress((void**)&KT, g_KT);

    static bool attr_done = false;
    if (!attr_done) {
        cudaFuncSetAttribute(gemm_tf32_pipe<true>,
                             cudaFuncAttributeMaxDynamicSharedMemorySize, SMEM_BYTES);
        cudaFuncSetAttribute(gemm_tf32_pipe<false>,
                             cudaFuncAttributeMaxDynamicSharedMemorySize, SMEM_BYTES);
        attr_done = true;
    }

    const int M = 8192, NBANK = 8192, D = 1024;
    const int ngroups = (M * D) / 8;

    stage_pairs_kernel<<<(ngroups + 255) / 256, 256>>>((const float4*)q, (float4*)QT, ngroups);
    stage_pairs_kernel<<<(ngroups + 255) / 256, 256>>>((const float4*)k, (float4*)KT, ngroups);
    transpose_kernel<<<dim3(D / 32, NBANK / 32), dim3(32, 8)>>>(v, VT, NBANK, D);

    // S = q @ k^T  (columns stored permuted = GEMM2's k layout)
    gemm_tf32_pipe<true><<<dim3(NBANK / BN, M / BM), 512, SMEM_BYTES>>>(QT, KT, S, M, NBANK, D);

    // norm + exact gelu in place (tf32-rounded output)
    norm_gelu_kernel<<<M, 256>>>(S, NBANK);

    // out = G @ vT^T
    gemm_tf32_pipe<false><<<dim3(D / BN, M / BM), 512, SMEM_BYTES>>>(S, VT, out, M, D, NBANK);
}